// round 7
// baseline (speedup 1.0000x reference)
#include <cuda_runtime.h>
#include <cstdint>

// RBF kernel, D=1 degenerate case:
//   out[b,i,j] = exp( -(x1[b,i] - x2[b,j])^2 / (2*scale^2) )
// B=4, N1=N2=8192. Output = 1.073 GB fp32 -> DRAM-write-drain bound.
//
// R7 probe: persistent single-wave kernel. Previous configs (4-16 waves of
// CTAs) all pinned DRAM at 89-90%; hypothesis: part of the ~10% idle is
// wave-transition / CTA ramp drain (T_wave_trans ~2360cyc x 15 transitions).
// Launch exactly one resident wave (148 SMs x 8 CTAs = 1184 blocks), each
// block grid-strides over ~28 (TI=8 x TJ=1024) tiles, keeping the store
// pipe continuously fed. Predicted: 140-142us if hypothesis holds, else
// noise-band neutral (143.5-145) => at HW ceiling, freeze.

static constexpr int B  = 4;
static constexpr int N1 = 8192;
static constexpr int N2 = 8192;
static constexpr int TI = 8;
static constexpr int TJ = 1024;            // 256 threads * float4
static constexpr int TILES_J = N2 / TJ;    // 8
static constexpr int TILES_I = N1 / TI;    // 1024
static constexpr int TILES   = B * TILES_I * TILES_J;  // 32768
static constexpr int NBLOCKS = 148 * 8;    // one full resident wave

__global__ __launch_bounds__(256, 8)
void rbf_kernel(const float* __restrict__ x1,
                const float* __restrict__ x2,
                const float* __restrict__ scale,
                float* __restrict__ out)
{
    const int tid = threadIdx.x;

    const float s = scale[0];
    const float c = -0.5f / (s * s);   // out = exp(c * d^2)

    for (int t = blockIdx.x; t < TILES; t += NBLOCKS) {
        // Decode tile: jb fast (adjacent blocks share an x2 chunk & write
        // adjacent j-spans), then it, then batch.
        const int jb  = t & (TILES_J - 1);          // 0..7
        const int rem = t >> 3;                     // t / TILES_J
        const int it  = rem & (TILES_I - 1);        // 0..1023
        const int b   = rem >> 10;                  // 0..3

        const int j  = jb * TJ + tid * 4;
        const int i0 = it * TI;

        // x2 chunk for this thread; x2 is L2-resident (32KB/batch).
        const float4 v2 = *reinterpret_cast<const float4*>(x2 + (size_t)b * N2 + j);

        const float* x1b = x1 + (size_t)b * N1 + i0;
        float* outb = out + ((size_t)b * N1 + i0) * (size_t)N2 + j;

#pragma unroll
        for (int r = 0; r < TI; ++r) {
            const float a = __ldg(x1b + r);   // uniform across block, L1-hot
            const float dx0 = a - v2.x;
            const float dx1 = a - v2.y;
            const float dx2 = a - v2.z;
            const float dx3 = a - v2.w;
            float4 o;
            o.x = __expf(c * dx0 * dx0);
            o.y = __expf(c * dx1 * dx1);
            o.z = __expf(c * dx2 * dx2);
            o.w = __expf(c * dx3 * dx3);
            *reinterpret_cast<float4*>(outb + (size_t)r * N2) = o;
        }
    }
}

extern "C" void kernel_launch(void* const* d_in, const int* in_sizes, int n_in,
                              void* d_out, int out_size)
{
    const float* x1    = (const float*)d_in[0];
    const float* x2    = (const float*)d_in[1];
    const float* scale = (const float*)d_in[2];
    float* out         = (float*)d_out;

    rbf_kernel<<<NBLOCKS, 256>>>(x1, x2, scale, out);
}

// round 8
// speedup vs baseline: 1.1919x; 1.1919x over previous
#include <cuda_runtime.h>
#include <cstdint>

// RBF kernel, D=1 degenerate case:
//   out[b,i,j] = exp( -(x1[b,i] - x2[b,j])^2 / (2*scale^2) )
// B=4, N1=N2=8192. Output = 1.073 GB fp32 -> pure DRAM-write-drain bound.
//
// FINAL. Best measured config (R2: 143.84us harness / 142.66us ncu):
//   TI=8 x TJ=1024 tile, 256 threads, one float4 of x2 in registers/thread,
//   scalar x1 broadcast loads (L1-hot), coalesced default-cache STG.E.128,
//   grid (8,1024,4) = 32768 CTAs (HW work-stealing makes waves free).
//
// Ceiling evidence (7 rounds): 5 store-scheme/tiling variants pin
// dram__cycles_active at 89-90% (~7.1 TB/s) with zero DRAM read traffic;
// persistent single-wave variant REGRESSED to 76.8% (loop-carried decode
// breaks store MLP). Residual ~10% idle = HBM write turnaround/refresh.
// No SM-side lever remains.

static constexpr int B  = 4;
static constexpr int N1 = 8192;
static constexpr int N2 = 8192;
static constexpr int TI = 8;
static constexpr int TJ = 1024;   // 256 threads * float4

__global__ __launch_bounds__(256, 8)
void rbf_kernel(const float* __restrict__ x1,
                const float* __restrict__ x2,
                const float* __restrict__ scale,
                float* __restrict__ out)
{
    const int tid = threadIdx.x;
    const int jb  = blockIdx.x;        // 0..N2/TJ-1  (8)
    const int it  = blockIdx.y;        // 0..N1/TI-1  (1024)
    const int b   = blockIdx.z;        // 0..B-1

    const int j  = jb * TJ + tid * 4;
    const int i0 = it * TI;

    // x2 chunk for this thread (registers); x2 is L2-resident (32KB/batch).
    const float4 v2 = *reinterpret_cast<const float4*>(x2 + (size_t)b * N2 + j);

    const float s = scale[0];
    const float c = -0.5f / (s * s);   // out = exp(c * d^2)

    const float* x1b = x1 + (size_t)b * N1 + i0;
    float* outb = out + ((size_t)b * N1 + i0) * (size_t)N2 + j;

#pragma unroll
    for (int r = 0; r < TI; ++r) {
        const float a = __ldg(x1b + r);   // uniform across block, L1-hot
        const float dx0 = a - v2.x;
        const float dx1 = a - v2.y;
        const float dx2 = a - v2.z;
        const float dx3 = a - v2.w;
        float4 o;
        o.x = __expf(c * dx0 * dx0);
        o.y = __expf(c * dx1 * dx1);
        o.z = __expf(c * dx2 * dx2);
        o.w = __expf(c * dx3 * dx3);
        *reinterpret_cast<float4*>(outb + (size_t)r * N2) = o;
    }
}

extern "C" void kernel_launch(void* const* d_in, const int* in_sizes, int n_in,
                              void* d_out, int out_size)
{
    const float* x1    = (const float*)d_in[0];
    const float* x2    = (const float*)d_in[1];
    const float* scale = (const float*)d_in[2];
    float* out         = (float*)d_out;

    dim3 grid(N2 / TJ, N1 / TI, B);   // (8, 1024, 4)
    rbf_kernel<<<grid, 256>>>(x1, x2, scale, out);
}